// round 16
// baseline (speedup 1.0000x reference)
#include <cuda_runtime.h>
#include <cuda_bf16.h>
#include <cstdint>
#include <math.h>

// Problem constants
#define SQ   2048
#define BB   2
#define DD   1024
#define HH   16
#define DHH  64
#define MROWS (SQ*BB)   // 4096

// ---------------------------------------------------------------------------
// Device scratch (no cudaMalloc allowed)
// ---------------------------------------------------------------------------
__device__ __nv_bfloat16 g_xhi[MROWS*DD];
__device__ __nv_bfloat16 g_xlo[MROWS*DD];
__device__ __nv_bfloat16 g_wthi[4][DD*DD];   // W^T as [N][K], bf16 hi
__device__ __nv_bfloat16 g_wtlo[4][DD*DD];   // bf16 lo
__device__ float g_q[BB*HH*SQ*DHH];
__device__ float g_k[BB*HH*SQ*DHH];
__device__ float g_v[BB*HH*SQ*DHH];
__device__ __nv_bfloat16 g_chi[MROWS*DD];
__device__ __nv_bfloat16 g_clo[MROWS*DD];

// ---------------------------------------------------------------------------
// PTX helpers (sm_80-class features only — NO tcgen05 / 'a'-features)
// ---------------------------------------------------------------------------
__device__ __forceinline__ uint32_t smem_to_u32(const void* p) {
    uint32_t a;
    asm("{ .reg .u64 t; cvta.to.shared.u64 t, %1; cvt.u32.u64 %0, t; }"
        : "=r"(a) : "l"(p));
    return a;
}

#define CP_ASYNC16(dst, src) \
    asm volatile("cp.async.cg.shared.global [%0], [%1], 16;" \
        :: "r"(dst), "l"(src) : "memory")
#define CP_COMMIT() asm volatile("cp.async.commit_group;" ::: "memory")
#define CP_WAIT0()  asm volatile("cp.async.wait_group 0;" ::: "memory")

#define LDSM_X4(r0, r1, r2, r3, addr) \
    asm volatile("ldmatrix.sync.aligned.m8n8.x4.shared.b16 {%0,%1,%2,%3}, [%4];" \
        : "=r"(r0), "=r"(r1), "=r"(r2), "=r"(r3) : "r"(addr))

#define MMA_BF16(c, a0, a1, a2, a3, b0, b1) \
    asm volatile("mma.sync.aligned.m16n8k16.row.col.f32.bf16.bf16.f32 " \
        "{%0,%1,%2,%3}, {%4,%5,%6,%7}, {%8,%9}, {%0,%1,%2,%3};" \
        : "+f"((c)[0]), "+f"((c)[1]), "+f"((c)[2]), "+f"((c)[3]) \
        : "r"(a0), "r"(a1), "r"(a2), "r"(a3), "r"(b0), "r"(b1))

// ---------------------------------------------------------------------------
// Prep kernels
// ---------------------------------------------------------------------------
__global__ void convert_split_kernel(const float* __restrict__ x,
                                     __nv_bfloat16* __restrict__ hi,
                                     __nv_bfloat16* __restrict__ lo, int n)
{
    int i = blockIdx.x * blockDim.x + threadIdx.x;
    if (i < n) {
        float v = x[i];
        __nv_bfloat16 h = __float2bfloat16(v);
        hi[i] = h;
        lo[i] = __float2bfloat16(v - __bfloat162float(h));
    }
}

// W [K=1024][N=1024] fp32 -> Wt_hi/lo [N][K] bf16
__global__ void transpose_split_kernel(const float* __restrict__ W,
                                       __nv_bfloat16* __restrict__ Thi,
                                       __nv_bfloat16* __restrict__ Tlo)
{
    __shared__ float t[32][33];
    const int k0 = blockIdx.y * 32, n0 = blockIdx.x * 32;
    const int tx = threadIdx.x, ty = threadIdx.y;
    #pragma unroll
    for (int j = 0; j < 32; j += 8)
        t[ty + j][tx] = W[(size_t)(k0 + ty + j) * DD + n0 + tx];
    __syncthreads();
    #pragma unroll
    for (int j = 0; j < 32; j += 8) {
        float v = t[tx][ty + j];
        __nv_bfloat16 h = __float2bfloat16(v);
        size_t o = (size_t)(n0 + ty + j) * DD + k0 + tx;
        Thi[o] = h;
        Tlo[o] = __float2bfloat16(v - __bfloat162float(h));
    }
}

// ---------------------------------------------------------------------------
// mma.sync bf16x3 GEMM: C(4096x1024) = A @ B^T
//   A [M][K] bf16 hi/lo, B [N][K] bf16 hi/lo (transposed weights).
//   CTA tile 128x256, BK=32, 8 warps (2M x 4N) each 64x64.
//   3 products: Ahi*Bhi + Ahi*Blo + Alo*Bhi  (fp32 accumulate)
//   EPI 0: row-major + bias; EPI 1: head scatter + bias; EPI 2: + q scale
// ---------------------------------------------------------------------------
#define BKC      32
#define NCH      (DD / BKC)       // 32
#define A_BYTES  10240            // 128 rows * 80B (padded)
#define B_BYTES  20480            // 256 rows * 80B
#define STG_BYTES (2*A_BYTES + 2*B_BYTES)   // 61440
#define GEMM_SMEM (2 * STG_BYTES)           // 122880

template<int EPI>
__global__ void __launch_bounds__(256, 1)
gemm_mma(const __nv_bfloat16* __restrict__ Ahi, const __nv_bfloat16* __restrict__ Alo,
         const __nv_bfloat16* __restrict__ Bhi, const __nv_bfloat16* __restrict__ Blo,
         const float* __restrict__ bias, const float* __restrict__ beta,
         float* __restrict__ C)
{
    extern __shared__ char smem[];
    const uint32_t sb = smem_to_u32(smem);
    const int tid  = threadIdx.x;
    const int lane = tid & 31;
    const int w    = tid >> 5;
    const int wm   = w & 1;          // 2 warps in M
    const int wn   = w >> 1;         // 4 warps in N
    const int bm = blockIdx.y * 128;
    const int bn = blockIdx.x * 256;
    const int m0w = wm * 64;
    const int n0w = wn * 64;

    float c[4][8][4];
    #pragma unroll
    for (int mi = 0; mi < 4; mi++)
        #pragma unroll
        for (int ni = 0; ni < 8; ni++)
            #pragma unroll
            for (int r = 0; r < 4; r++) c[mi][ni][r] = 0.f;

    auto load_chunk = [&](int ch, int s) {
        const int kt = ch * BKC;
        const uint32_t base = sb + s * STG_BYTES;
        // A: 128 rows x 32 bf16 = 4 x uint4 per row (hi & lo)
        #pragma unroll
        for (int i = tid; i < 512; i += 256) {
            int r = i >> 2, g = i & 3;
            uint32_t off = (uint32_t)(r * 80 + g * 16);
            const char* ph = (const char*)(Ahi + (size_t)(bm + r) * DD + kt) + g * 16;
            const char* pl = (const char*)(Alo + (size_t)(bm + r) * DD + kt) + g * 16;
            CP_ASYNC16(base + off, ph);
            CP_ASYNC16(base + A_BYTES + off, pl);
        }
        // B: 256 rows
        #pragma unroll
        for (int i = tid; i < 1024; i += 256) {
            int r = i >> 2, g = i & 3;
            uint32_t off = (uint32_t)(r * 80 + g * 16);
            const char* ph = (const char*)(Bhi + (size_t)(bn + r) * DD + kt) + g * 16;
            const char* pl = (const char*)(Blo + (size_t)(bn + r) * DD + kt) + g * 16;
            CP_ASYNC16(base + 2 * A_BYTES + off, ph);
            CP_ASYNC16(base + 2 * A_BYTES + B_BYTES + off, pl);
        }
        CP_COMMIT();
    };

    // per-lane ldmatrix offset parts (same pattern for A and B, non-trans):
    // row = tile_row0 + (lane & 15), kcol = ks + (lane>>4)*8
    const uint32_t lrow = (uint32_t)(lane & 15);
    const uint32_t lk   = (uint32_t)((lane >> 4) << 3);

    load_chunk(0, 0);
    CP_WAIT0();
    __syncthreads();

    for (int ch = 0; ch < NCH; ch++) {
        const int s = ch & 1;
        if (ch + 1 < NCH) load_chunk(ch + 1, s ^ 1);

        const uint32_t base = sb + s * STG_BYTES;
        #pragma unroll
        for (int ks = 0; ks < BKC; ks += 16) {
            uint32_t bh[4][4], bl[4][4];
            #pragma unroll
            for (int np = 0; np < 4; np++) {
                uint32_t ba = base + 2 * A_BYTES +
                    (uint32_t)(((n0w + np * 16 + lrow) * 40 + ks) * 2) + lk * 2;
                LDSM_X4(bh[np][0], bh[np][1], bh[np][2], bh[np][3], ba);
                LDSM_X4(bl[np][0], bl[np][1], bl[np][2], bl[np][3], ba + B_BYTES);
            }
            #pragma unroll
            for (int mi = 0; mi < 4; mi++) {
                uint32_t aa = base +
                    (uint32_t)(((m0w + mi * 16 + lrow) * 40 + ks) * 2) + lk * 2;
                uint32_t ah[4], al[4];
                LDSM_X4(ah[0], ah[1], ah[2], ah[3], aa);
                LDSM_X4(al[0], al[1], al[2], al[3], aa + A_BYTES);
                #pragma unroll
                for (int np = 0; np < 4; np++) {
                    // n-tile 2*np uses regs (x[np][0], x[np][2]); 2*np+1 uses ([1],[3])
                    MMA_BF16(c[mi][2*np],   ah[0], ah[1], ah[2], ah[3], bh[np][0], bh[np][2]);
                    MMA_BF16(c[mi][2*np],   ah[0], ah[1], ah[2], ah[3], bl[np][0], bl[np][2]);
                    MMA_BF16(c[mi][2*np],   al[0], al[1], al[2], al[3], bh[np][0], bh[np][2]);
                    MMA_BF16(c[mi][2*np+1], ah[0], ah[1], ah[2], ah[3], bh[np][1], bh[np][3]);
                    MMA_BF16(c[mi][2*np+1], ah[0], ah[1], ah[2], ah[3], bl[np][1], bl[np][3]);
                    MMA_BF16(c[mi][2*np+1], al[0], al[1], al[2], al[3], bh[np][1], bh[np][3]);
                }
            }
        }
        if (ch + 1 < NCH) CP_WAIT0();
        __syncthreads();
    }

    // Epilogue: fragment (mi,ni): rows m0+mi*16+lane/4 (+8), cols n0+ni*8+(lane%4)*2
    #pragma unroll
    for (int mi = 0; mi < 4; mi++) {
        #pragma unroll
        for (int ni = 0; ni < 8; ni++) {
            const int row = bm + m0w + mi * 16 + (lane >> 2);
            const int col = bn + n0w + ni * 8 + (lane & 3) * 2;
            const float b0 = __ldg(&bias[col]);
            const float b1 = __ldg(&bias[col + 1]);
            const float* cc = c[mi][ni];
            if (EPI == 0) {
                float2 v0 = make_float2(cc[0] + b0, cc[1] + b1);
                float2 v1 = make_float2(cc[2] + b0, cc[3] + b1);
                *(float2*)&C[(size_t)row * DD + col] = v0;
                *(float2*)&C[(size_t)(row + 8) * DD + col] = v1;
            } else {
                const int h  = col >> 6;
                const int dh = col & 63;
                const float sc = (EPI == 2) ? 0.125f * __expf(-__ldg(&beta[h])) : 1.0f;
                // row r -> s = r>>1, b = r&1; out[(b*H+h)*S + s][dh]
                {
                    const int srow = row >> 1, brow = row & 1;
                    float2 v = make_float2((cc[0] + b0) * sc, (cc[1] + b1) * sc);
                    *(float2*)&C[(((size_t)(brow * HH + h)) * SQ + srow) * DHH + dh] = v;
                }
                {
                    const int r2 = row + 8;
                    const int srow = r2 >> 1, brow = r2 & 1;
                    float2 v = make_float2((cc[2] + b0) * sc, (cc[3] + b1) * sc);
                    *(float2*)&C[(((size_t)(brow * HH + h)) * SQ + srow) * DHH + dh] = v;
                }
            }
        }
    }
}

// ---------------------------------------------------------------------------
// Attention: K in smem (padded), V streamed from L2, P aliases K region.
// smem = 320*65 + 64*64 floats = 99584 B -> 2 CTAs/SM.
// ---------------------------------------------------------------------------
__global__ void __launch_bounds__(256, 2)
attn_kernel(const float* __restrict__ Q, const float* __restrict__ K,
            const float* __restrict__ V,
            __nv_bfloat16* __restrict__ Chi, __nv_bfloat16* __restrict__ Clo)
{
    extern __shared__ float sm[];
    float* Ksm = sm;                 // 320*65 = 20800 floats
    float* Qsm = sm + 320 * 65;      // 64*64  = 4096 floats
    float* Psm = sm;                 // alias Ksm: 64*320 = 20480 floats

    const int tid   = threadIdx.x;
    const int z     = blockIdx.y;
    const int q0    = blockIdx.x * 64;
    const int kbase = q0 - 256;
    const size_t base = (size_t)z * SQ * DHH;

    #pragma unroll
    for (int t = 0; t < 4; t++) {
        int i4 = tid + t * 256;
        int qi = i4 >> 4;
        int d4 = (i4 & 15) * 4;
        *(float4*)&Qsm[qi * 64 + d4] =
            *(const float4*)&Q[base + (size_t)(q0 + qi) * DHH + d4];
    }
    for (int idx = tid; idx < 320 * 64; idx += 256) {
        int j = idx >> 6, d = idx & 63;
        int kp = kbase + j;
        Ksm[j * 65 + d] = (kp >= 0) ? K[base + (size_t)kp * DHH + d] : 0.f;
    }
    __syncthreads();

    const int w = tid >> 5, lane = tid & 31;
    float acc[8][10];
    #pragma unroll
    for (int i = 0; i < 8; i++)
        #pragma unroll
        for (int j = 0; j < 10; j++) acc[i][j] = 0.f;

    const float* qrow = Qsm + (w * 8) * 64;
    #pragma unroll 4
    for (int d = 0; d < 64; d++) {
        float qv[8];
        #pragma unroll
        for (int i = 0; i < 8; i++) qv[i] = qrow[i * 64 + d];
        float kv[10];
        #pragma unroll
        for (int j = 0; j < 10; j++) kv[j] = Ksm[(lane + 32 * j) * 65 + d];
        #pragma unroll
        for (int i = 0; i < 8; i++)
            #pragma unroll
            for (int j = 0; j < 10; j++)
                acc[i][j] += qv[i] * kv[j];
    }

    #pragma unroll
    for (int i = 0; i < 8; i++) {
        const int qloc = w * 8 + i;
        float m = 0.f;   // sink logit 0 included in max
        #pragma unroll
        for (int j = 0; j < 10; j++) {
            int jj = lane + 32 * j;
            bool ok = (jj > qloc) && (jj <= qloc + 256) && (kbase + jj >= 0);
            if (!ok) acc[i][j] = -1e30f;
            m = fmaxf(m, acc[i][j]);
        }
        #pragma unroll
        for (int off = 16; off > 0; off >>= 1)
            m = fmaxf(m, __shfl_xor_sync(0xffffffffu, m, off));
        float ssum = 0.f;
        #pragma unroll
        for (int j = 0; j < 10; j++) {
            float p = (acc[i][j] > -1e29f) ? __expf(acc[i][j] - m) : 0.f;
            acc[i][j] = p;
            ssum += p;
        }
        #pragma unroll
        for (int off = 16; off > 0; off >>= 1)
            ssum += __shfl_xor_sync(0xffffffffu, ssum, off);
        const float inv = 1.f / (ssum + __expf(-m));   // + sink mass
        #pragma unroll
        for (int j = 0; j < 10; j++) acc[i][j] *= inv;
    }

    __syncthreads();   // all warps done reading Ksm
    #pragma unroll
    for (int i = 0; i < 8; i++)
        #pragma unroll
        for (int j = 0; j < 10; j++)
            Psm[(w * 8 + i) * 320 + lane + 32 * j] = acc[i][j];
    __syncthreads();

    // O = P @ V, V streamed from global (L2-resident). Masked P entries are 0.
    const int d  = tid & 63;
    const int qg = tid >> 6;
    const float* Vz = V + base;
    float o[16];
    #pragma unroll
    for (int t = 0; t < 16; t++) o[t] = 0.f;
    #pragma unroll 4
    for (int k = 0; k < 320; k++) {
        int kp = kbase + k;
        int kc = kp < 0 ? 0 : kp;
        float vv = __ldg(&Vz[(size_t)kc * DHH + d]);
        #pragma unroll
        for (int t = 0; t < 16; t++)
            o[t] += Psm[(qg + 4 * t) * 320 + k] * vv;
    }
    const int b = z >> 4, h = z & 15;
    #pragma unroll
    for (int t = 0; t < 16; t++) {
        const int qi = qg + 4 * t;
        const size_t idx = ((size_t)(q0 + qi) * BB + b) * DD + h * DHH + d;
        const float val = o[t];
        __nv_bfloat16 hi = __float2bfloat16(val);
        Chi[idx] = hi;
        Clo[idx] = __float2bfloat16(val - __bfloat162float(hi));
    }
}

// ---------------------------------------------------------------------------
extern "C" void kernel_launch(void* const* d_in, const int* in_sizes, int n_in,
                              void* d_out, int out_size)
{
    const float* x    = (const float*)d_in[0];
    const float* beta = (const float*)d_in[1];
    const float* Wq   = (const float*)d_in[2];
    const float* bq   = (const float*)d_in[3];
    const float* Wk   = (const float*)d_in[4];
    const float* bk   = (const float*)d_in[5];
    const float* Wv   = (const float*)d_in[6];
    const float* bv   = (const float*)d_in[7];
    const float* Wo   = (const float*)d_in[8];
    const float* bo   = (const float*)d_in[9];
    float* out = (float*)d_out;

    __nv_bfloat16 *xhi, *xlo, *wthi, *wtlo, *chi, *clo;
    float *q, *k, *v;
    cudaGetSymbolAddress((void**)&xhi,  g_xhi);
    cudaGetSymbolAddress((void**)&xlo,  g_xlo);
    cudaGetSymbolAddress((void**)&wthi, g_wthi);
    cudaGetSymbolAddress((void**)&wtlo, g_wtlo);
    cudaGetSymbolAddress((void**)&q,    g_q);
    cudaGetSymbolAddress((void**)&k,    g_k);
    cudaGetSymbolAddress((void**)&v,    g_v);
    cudaGetSymbolAddress((void**)&chi,  g_chi);
    cudaGetSymbolAddress((void**)&clo,  g_clo);

    // --- prep: split x, transpose+split weights ---
    convert_split_kernel<<<(MROWS * DD + 255) / 256, 256>>>(x, xhi, xlo, MROWS * DD);
    const float* Ws[4] = { Wq, Wk, Wv, Wo };
    for (int i = 0; i < 4; i++)
        transpose_split_kernel<<<dim3(32, 32), dim3(32, 8)>>>(
            Ws[i], wthi + (size_t)i * DD * DD, wtlo + (size_t)i * DD * DD);

    // --- mma.sync GEMMs ---
    cudaFuncSetAttribute(gemm_mma<0>, cudaFuncAttributeMaxDynamicSharedMemorySize, GEMM_SMEM);
    cudaFuncSetAttribute(gemm_mma<1>, cudaFuncAttributeMaxDynamicSharedMemorySize, GEMM_SMEM);
    cudaFuncSetAttribute(gemm_mma<2>, cudaFuncAttributeMaxDynamicSharedMemorySize, GEMM_SMEM);
    const dim3 gg(DD / 256, MROWS / 128);   // (4, 32) = 128 CTAs

    gemm_mma<2><<<gg, 256, GEMM_SMEM>>>(xhi, xlo,
        wthi + 0 * (size_t)DD * DD, wtlo + 0 * (size_t)DD * DD, bq, beta, q);
    gemm_mma<1><<<gg, 256, GEMM_SMEM>>>(xhi, xlo,
        wthi + 1 * (size_t)DD * DD, wtlo + 1 * (size_t)DD * DD, bk, nullptr, k);
    gemm_mma<1><<<gg, 256, GEMM_SMEM>>>(xhi, xlo,
        wthi + 2 * (size_t)DD * DD, wtlo + 2 * (size_t)DD * DD, bv, nullptr, v);

    // --- attention ---
    const int ATTN_SMEM = (320 * 65 + 64 * 64) * (int)sizeof(float);   // 99584
    cudaFuncSetAttribute(attn_kernel, cudaFuncAttributeMaxDynamicSharedMemorySize, ATTN_SMEM);
    attn_kernel<<<dim3(SQ / 64, BB * HH), 256, ATTN_SMEM>>>(q, k, v, chi, clo);

    // --- output projection straight into d_out ---
    gemm_mma<0><<<gg, 256, GEMM_SMEM>>>(chi, clo,
        wthi + 3 * (size_t)DD * DD, wtlo + 3 * (size_t)DD * DD, bo, nullptr, out);
}

// round 17
// speedup vs baseline: 1.0238x; 1.0238x over previous
#include <cuda_runtime.h>
#include <cuda_bf16.h>
#include <cstdint>
#include <math.h>

// Problem constants
#define SQ   2048
#define BB   2
#define DD   1024
#define HH   16
#define DHH  64
#define MROWS (SQ*BB)   // 4096

// ---------------------------------------------------------------------------
// Device scratch (no cudaMalloc allowed)
// ---------------------------------------------------------------------------
__device__ __nv_bfloat16 g_xhi[MROWS*DD];
__device__ __nv_bfloat16 g_xlo[MROWS*DD];
__device__ __nv_bfloat16 g_wthi[4][DD*DD];   // W^T as [N][K], bf16 hi
__device__ __nv_bfloat16 g_wtlo[4][DD*DD];   // bf16 lo
__device__ float g_q[BB*HH*SQ*DHH];
__device__ float g_k[BB*HH*SQ*DHH];
__device__ float g_v[BB*HH*SQ*DHH];
__device__ __nv_bfloat16 g_chi[MROWS*DD];
__device__ __nv_bfloat16 g_clo[MROWS*DD];

// ---------------------------------------------------------------------------
// PTX helpers (sm_80-class features only)
// ---------------------------------------------------------------------------
__device__ __forceinline__ uint32_t smem_to_u32(const void* p) {
    uint32_t a;
    asm("{ .reg .u64 t; cvta.to.shared.u64 t, %1; cvt.u32.u64 %0, t; }"
        : "=r"(a) : "l"(p));
    return a;
}

#define CP_ASYNC16(dst, src) \
    asm volatile("cp.async.cg.shared.global [%0], [%1], 16;" \
        :: "r"(dst), "l"(src) : "memory")
#define CP_COMMIT() asm volatile("cp.async.commit_group;" ::: "memory")
#define CP_WAIT0()  asm volatile("cp.async.wait_group 0;" ::: "memory")

#define LDSM_X4(r0, r1, r2, r3, addr) \
    asm volatile("ldmatrix.sync.aligned.m8n8.x4.shared.b16 {%0,%1,%2,%3}, [%4];" \
        : "=r"(r0), "=r"(r1), "=r"(r2), "=r"(r3) : "r"(addr))

#define MMA_BF16(c, a0, a1, a2, a3, b0, b1) \
    asm volatile("mma.sync.aligned.m16n8k16.row.col.f32.bf16.bf16.f32 " \
        "{%0,%1,%2,%3}, {%4,%5,%6,%7}, {%8,%9}, {%0,%1,%2,%3};" \
        : "+f"((c)[0]), "+f"((c)[1]), "+f"((c)[2]), "+f"((c)[3]) \
        : "r"(a0), "r"(a1), "r"(a2), "r"(a3), "r"(b0), "r"(b1))

// ---------------------------------------------------------------------------
// Prep kernels
// ---------------------------------------------------------------------------
__global__ void convert_split_kernel(const float* __restrict__ x,
                                     __nv_bfloat16* __restrict__ hi,
                                     __nv_bfloat16* __restrict__ lo, int n)
{
    int i = blockIdx.x * blockDim.x + threadIdx.x;
    if (i < n) {
        float v = x[i];
        __nv_bfloat16 h = __float2bfloat16(v);
        hi[i] = h;
        lo[i] = __float2bfloat16(v - __bfloat162float(h));
    }
}

// All 4 weights in one launch (grid.z selects weight)
__global__ void transpose_split_kernel(const float* __restrict__ W0,
                                       const float* __restrict__ W1,
                                       const float* __restrict__ W2,
                                       const float* __restrict__ W3,
                                       __nv_bfloat16* __restrict__ Thi,
                                       __nv_bfloat16* __restrict__ Tlo)
{
    __shared__ float t[32][33];
    const int wsel = blockIdx.z;
    const float* W = (wsel == 0) ? W0 : (wsel == 1) ? W1 : (wsel == 2) ? W2 : W3;
    __nv_bfloat16* thi = Thi + (size_t)wsel * DD * DD;
    __nv_bfloat16* tlo = Tlo + (size_t)wsel * DD * DD;
    const int k0 = blockIdx.y * 32, n0 = blockIdx.x * 32;
    const int tx = threadIdx.x, ty = threadIdx.y;
    #pragma unroll
    for (int j = 0; j < 32; j += 8)
        t[ty + j][tx] = W[(size_t)(k0 + ty + j) * DD + n0 + tx];
    __syncthreads();
    #pragma unroll
    for (int j = 0; j < 32; j += 8) {
        float v = t[tx][ty + j];
        __nv_bfloat16 h = __float2bfloat16(v);
        size_t o = (size_t)(n0 + ty + j) * DD + k0 + tx;
        thi[o] = h;
        tlo[o] = __float2bfloat16(v - __bfloat162float(h));
    }
}

// ---------------------------------------------------------------------------
// mma.sync bf16x3 GEMM: C(4096x1024) = A @ B^T
//   CTA tile 128x128, BK=32, 2 CTAs/SM, 8 warps (2M x 4N) each 64x32.
//   3 products: Ahi*Bhi + Ahi*Blo + Alo*Bhi  (fp32 accumulate)
// ---------------------------------------------------------------------------
#define BKC      32
#define NCH      (DD / BKC)       // 32
#define A_BYTES  10240            // 128 rows * 80B (padded)
#define B_BYTES  10240            // 128 rows * 80B
#define STG_BYTES (2*A_BYTES + 2*B_BYTES)   // 40960
#define GEMM_SMEM (2 * STG_BYTES)           // 81920

template<int EPI>
__global__ void __launch_bounds__(256, 2)
gemm_mma(const __nv_bfloat16* __restrict__ Ahi, const __nv_bfloat16* __restrict__ Alo,
         const __nv_bfloat16* __restrict__ Bhi, const __nv_bfloat16* __restrict__ Blo,
         const float* __restrict__ bias, const float* __restrict__ beta,
         float* __restrict__ C)
{
    extern __shared__ char smem[];
    const uint32_t sb = smem_to_u32(smem);
    const int tid  = threadIdx.x;
    const int lane = tid & 31;
    const int w    = tid >> 5;
    const int wm   = w & 1;          // 2 warps in M
    const int wn   = w >> 1;         // 4 warps in N
    const int bm = blockIdx.y * 128;
    const int bn = blockIdx.x * 128;
    const int m0w = wm * 64;
    const int n0w = wn * 32;

    float c[4][4][4];
    #pragma unroll
    for (int mi = 0; mi < 4; mi++)
        #pragma unroll
        for (int ni = 0; ni < 4; ni++)
            #pragma unroll
            for (int r = 0; r < 4; r++) c[mi][ni][r] = 0.f;

    auto load_chunk = [&](int ch, int s) {
        const int kt = ch * BKC;
        const uint32_t base = sb + s * STG_BYTES;
        // A and B: each 128 rows x 32 bf16 = 4 x 16B per row (hi & lo)
        #pragma unroll
        for (int i = tid; i < 512; i += 256) {
            int r = i >> 2, g = i & 3;
            uint32_t off = (uint32_t)(r * 80 + g * 16);
            const char* pah = (const char*)(Ahi + (size_t)(bm + r) * DD + kt) + g * 16;
            const char* pal = (const char*)(Alo + (size_t)(bm + r) * DD + kt) + g * 16;
            const char* pbh = (const char*)(Bhi + (size_t)(bn + r) * DD + kt) + g * 16;
            const char* pbl = (const char*)(Blo + (size_t)(bn + r) * DD + kt) + g * 16;
            CP_ASYNC16(base + off, pah);
            CP_ASYNC16(base + A_BYTES + off, pal);
            CP_ASYNC16(base + 2 * A_BYTES + off, pbh);
            CP_ASYNC16(base + 2 * A_BYTES + B_BYTES + off, pbl);
        }
        CP_COMMIT();
    };

    const uint32_t lrow = (uint32_t)(lane & 15);
    const uint32_t lk   = (uint32_t)((lane >> 4) << 3);

    load_chunk(0, 0);
    CP_WAIT0();
    __syncthreads();

    for (int ch = 0; ch < NCH; ch++) {
        const int s = ch & 1;
        if (ch + 1 < NCH) load_chunk(ch + 1, s ^ 1);

        const uint32_t base = sb + s * STG_BYTES;
        #pragma unroll
        for (int ks = 0; ks < BKC; ks += 16) {
            uint32_t bh[2][4], bl[2][4];
            #pragma unroll
            for (int np = 0; np < 2; np++) {
                uint32_t ba = base + 2 * A_BYTES +
                    (uint32_t)(((n0w + np * 16 + lrow) * 40 + ks) * 2) + lk * 2;
                LDSM_X4(bh[np][0], bh[np][1], bh[np][2], bh[np][3], ba);
                LDSM_X4(bl[np][0], bl[np][1], bl[np][2], bl[np][3], ba + B_BYTES);
            }
            #pragma unroll
            for (int mi = 0; mi < 4; mi++) {
                uint32_t aa = base +
                    (uint32_t)(((m0w + mi * 16 + lrow) * 40 + ks) * 2) + lk * 2;
                uint32_t ah[4], al[4];
                LDSM_X4(ah[0], ah[1], ah[2], ah[3], aa);
                LDSM_X4(al[0], al[1], al[2], al[3], aa + A_BYTES);
                #pragma unroll
                for (int np = 0; np < 2; np++) {
                    MMA_BF16(c[mi][2*np],   ah[0], ah[1], ah[2], ah[3], bh[np][0], bh[np][2]);
                    MMA_BF16(c[mi][2*np],   ah[0], ah[1], ah[2], ah[3], bl[np][0], bl[np][2]);
                    MMA_BF16(c[mi][2*np],   al[0], al[1], al[2], al[3], bh[np][0], bh[np][2]);
                    MMA_BF16(c[mi][2*np+1], ah[0], ah[1], ah[2], ah[3], bh[np][1], bh[np][3]);
                    MMA_BF16(c[mi][2*np+1], ah[0], ah[1], ah[2], ah[3], bl[np][1], bl[np][3]);
                    MMA_BF16(c[mi][2*np+1], al[0], al[1], al[2], al[3], bh[np][1], bh[np][3]);
                }
            }
        }
        if (ch + 1 < NCH) CP_WAIT0();
        __syncthreads();
    }

    // Epilogue
    #pragma unroll
    for (int mi = 0; mi < 4; mi++) {
        #pragma unroll
        for (int ni = 0; ni < 4; ni++) {
            const int row = bm + m0w + mi * 16 + (lane >> 2);
            const int col = bn + n0w + ni * 8 + (lane & 3) * 2;
            const float b0 = __ldg(&bias[col]);
            const float b1 = __ldg(&bias[col + 1]);
            const float* cc = c[mi][ni];
            if (EPI == 0) {
                float2 v0 = make_float2(cc[0] + b0, cc[1] + b1);
                float2 v1 = make_float2(cc[2] + b0, cc[3] + b1);
                *(float2*)&C[(size_t)row * DD + col] = v0;
                *(float2*)&C[(size_t)(row + 8) * DD + col] = v1;
            } else {
                const int h  = col >> 6;
                const int dh = col & 63;
                const float sc = (EPI == 2) ? 0.125f * __expf(-__ldg(&beta[h])) : 1.0f;
                {
                    const int srow = row >> 1, brow = row & 1;
                    float2 v = make_float2((cc[0] + b0) * sc, (cc[1] + b1) * sc);
                    *(float2*)&C[(((size_t)(brow * HH + h)) * SQ + srow) * DHH + dh] = v;
                }
                {
                    const int r2 = row + 8;
                    const int srow = r2 >> 1, brow = r2 & 1;
                    float2 v = make_float2((cc[2] + b0) * sc, (cc[3] + b1) * sc);
                    *(float2*)&C[(((size_t)(brow * HH + h)) * SQ + srow) * DHH + dh] = v;
                }
            }
        }
    }
}

// ---------------------------------------------------------------------------
// Attention: K in smem, V streamed from L2, P stored TRANSPOSED [k][q]
// (stride 68 floats, 16B-aligned rows) so the PV pass reads float4 broadcasts.
// smem = max(320*65 + 64*64, 320*68) = 24896 floats = 99584 B -> 2 CTAs/SM.
// ---------------------------------------------------------------------------
__global__ void __launch_bounds__(256, 2)
attn_kernel(const float* __restrict__ Q, const float* __restrict__ K,
            const float* __restrict__ V,
            __nv_bfloat16* __restrict__ Chi, __nv_bfloat16* __restrict__ Clo)
{
    extern __shared__ float sm[];
    float* Ksm = sm;                 // 320*65 = 20800 floats
    float* Qsm = sm + 320 * 65;      // 64*64  = 4096 floats
    float* Psm = sm;                 // alias: 320*68 = 21760 floats (covers Ksm + head of Qsm)

    const int tid   = threadIdx.x;
    const int z     = blockIdx.y;
    const int q0    = blockIdx.x * 64;
    const int kbase = q0 - 256;
    const size_t base = (size_t)z * SQ * DHH;

    #pragma unroll
    for (int t = 0; t < 4; t++) {
        int i4 = tid + t * 256;
        int qi = i4 >> 4;
        int d4 = (i4 & 15) * 4;
        *(float4*)&Qsm[qi * 64 + d4] =
            *(const float4*)&Q[base + (size_t)(q0 + qi) * DHH + d4];
    }
    for (int idx = tid; idx < 320 * 64; idx += 256) {
        int j = idx >> 6, d = idx & 63;
        int kp = kbase + j;
        Ksm[j * 65 + d] = (kp >= 0) ? K[base + (size_t)kp * DHH + d] : 0.f;
    }
    __syncthreads();

    const int w = tid >> 5, lane = tid & 31;
    float acc[8][10];
    #pragma unroll
    for (int i = 0; i < 8; i++)
        #pragma unroll
        for (int j = 0; j < 10; j++) acc[i][j] = 0.f;

    const float* qrow = Qsm + (w * 8) * 64;
    #pragma unroll 4
    for (int d = 0; d < 64; d++) {
        float qv[8];
        #pragma unroll
        for (int i = 0; i < 8; i++) qv[i] = qrow[i * 64 + d];
        float kv[10];
        #pragma unroll
        for (int j = 0; j < 10; j++) kv[j] = Ksm[(lane + 32 * j) * 65 + d];
        #pragma unroll
        for (int i = 0; i < 8; i++)
            #pragma unroll
            for (int j = 0; j < 10; j++)
                acc[i][j] += qv[i] * kv[j];
    }

    #pragma unroll
    for (int i = 0; i < 8; i++) {
        const int qloc = w * 8 + i;
        float m = 0.f;   // sink logit 0 included in max
        #pragma unroll
        for (int j = 0; j < 10; j++) {
            int jj = lane + 32 * j;
            bool ok = (jj > qloc) && (jj <= qloc + 256) && (kbase + jj >= 0);
            if (!ok) acc[i][j] = -1e30f;
            m = fmaxf(m, acc[i][j]);
        }
        #pragma unroll
        for (int off = 16; off > 0; off >>= 1)
            m = fmaxf(m, __shfl_xor_sync(0xffffffffu, m, off));
        float ssum = 0.f;
        #pragma unroll
        for (int j = 0; j < 10; j++) {
            float p = (acc[i][j] > -1e29f) ? __expf(acc[i][j] - m) : 0.f;
            acc[i][j] = p;
            ssum += p;
        }
        #pragma unroll
        for (int off = 16; off > 0; off >>= 1)
            ssum += __shfl_xor_sync(0xffffffffu, ssum, off);
        const float inv = 1.f / (ssum + __expf(-m));   // + sink mass
        #pragma unroll
        for (int j = 0; j < 10; j++) acc[i][j] *= inv;
    }

    __syncthreads();   // all warps done reading Ksm/Qsm
    // store P transposed: Psm[k*68 + q], float4-packed over q
    #pragma unroll
    for (int j = 0; j < 10; j++) {
        const int krow = lane + 32 * j;
        *(float4*)&Psm[krow * 68 + w * 8] =
            make_float4(acc[0][j], acc[1][j], acc[2][j], acc[3][j]);
        *(float4*)&Psm[krow * 68 + w * 8 + 4] =
            make_float4(acc[4][j], acc[5][j], acc[6][j], acc[7][j]);
    }
    __syncthreads();

    // O = P^T-read @ V. Thread owns dim d, contiguous q-range qg*16..qg*16+15.
    const int d  = tid & 63;
    const int qg = tid >> 6;   // 0..3
    const float* Vz = V + base;
    const float4* P4 = (const float4*)Psm;
    float o[16];
    #pragma unroll
    for (int t = 0; t < 16; t++) o[t] = 0.f;
    #pragma unroll 4
    for (int k = 0; k < 320; k++) {
        int kp = kbase + k;
        int kc = kp < 0 ? 0 : kp;
        float vv = __ldg(&Vz[(size_t)kc * DHH + d]);
        float4 p0 = P4[k * 17 + qg * 4 + 0];
        float4 p1 = P4[k * 17 + qg * 4 + 1];
        float4 p2 = P4[k * 17 + qg * 4 + 2];
        float4 p3 = P4[k * 17 + qg * 4 + 3];
        o[0]  += p0.x * vv;  o[1]  += p0.y * vv;  o[2]  += p0.z * vv;  o[3]  += p0.w * vv;
        o[4]  += p1.x * vv;  o[5]  += p1.y * vv;  o[6]  += p1.z * vv;  o[7]  += p1.w * vv;
        o[8]  += p2.x * vv;  o[9]  += p2.y * vv;  o[10] += p2.z * vv;  o[11] += p2.w * vv;
        o[12] += p3.x * vv;  o[13] += p3.y * vv;  o[14] += p3.z * vv;  o[15] += p3.w * vv;
    }
    const int b = z >> 4, h = z & 15;
    #pragma unroll
    for (int t = 0; t < 16; t++) {
        const int qi = qg * 16 + t;
        const size_t idx = ((size_t)(q0 + qi) * BB + b) * DD + h * DHH + d;
        const float val = o[t];
        __nv_bfloat16 hi = __float2bfloat16(val);
        Chi[idx] = hi;
        Clo[idx] = __float2bfloat16(val - __bfloat162float(hi));
    }
}

// ---------------------------------------------------------------------------
extern "C" void kernel_launch(void* const* d_in, const int* in_sizes, int n_in,
                              void* d_out, int out_size)
{
    const float* x    = (const float*)d_in[0];
    const float* beta = (const float*)d_in[1];
    const float* Wq   = (const float*)d_in[2];
    const float* bq   = (const float*)d_in[3];
    const float* Wk   = (const float*)d_in[4];
    const float* bk   = (const float*)d_in[5];
    const float* Wv   = (const float*)d_in[6];
    const float* bv   = (const float*)d_in[7];
    const float* Wo   = (const float*)d_in[8];
    const float* bo   = (const float*)d_in[9];
    float* out = (float*)d_out;

    __nv_bfloat16 *xhi, *xlo, *wthi, *wtlo, *chi, *clo;
    float *q, *k, *v;
    cudaGetSymbolAddress((void**)&xhi,  g_xhi);
    cudaGetSymbolAddress((void**)&xlo,  g_xlo);
    cudaGetSymbolAddress((void**)&wthi, g_wthi);
    cudaGetSymbolAddress((void**)&wtlo, g_wtlo);
    cudaGetSymbolAddress((void**)&q,    g_q);
    cudaGetSymbolAddress((void**)&k,    g_k);
    cudaGetSymbolAddress((void**)&v,    g_v);
    cudaGetSymbolAddress((void**)&chi,  g_chi);
    cudaGetSymbolAddress((void**)&clo,  g_clo);

    // --- prep ---
    convert_split_kernel<<<(MROWS * DD + 255) / 256, 256>>>(x, xhi, xlo, MROWS * DD);
    transpose_split_kernel<<<dim3(32, 32, 4), dim3(32, 8)>>>(
        Wq, Wk, Wv, Wo, wthi, wtlo);

    // --- mma.sync GEMMs (128x128 tiles, 2 CTAs/SM) ---
    cudaFuncSetAttribute(gemm_mma<0>, cudaFuncAttributeMaxDynamicSharedMemorySize, GEMM_SMEM);
    cudaFuncSetAttribute(gemm_mma<1>, cudaFuncAttributeMaxDynamicSharedMemorySize, GEMM_SMEM);
    cudaFuncSetAttribute(gemm_mma<2>, cudaFuncAttributeMaxDynamicSharedMemorySize, GEMM_SMEM);
    const dim3 gg(DD / 128, MROWS / 128);   // (8, 32) = 256 CTAs

    gemm_mma<2><<<gg, 256, GEMM_SMEM>>>(xhi, xlo,
        wthi + 0 * (size_t)DD * DD, wtlo + 0 * (size_t)DD * DD, bq, beta, q);
    gemm_mma<1><<<gg, 256, GEMM_SMEM>>>(xhi, xlo,
        wthi + 1 * (size_t)DD * DD, wtlo + 1 * (size_t)DD * DD, bk, nullptr, k);
    gemm_mma<1><<<gg, 256, GEMM_SMEM>>>(xhi, xlo,
        wthi + 2 * (size_t)DD * DD, wtlo + 2 * (size_t)DD * DD, bv, nullptr, v);

    // --- attention ---
    const int ATTN_SMEM = (320 * 65 + 64 * 64) * (int)sizeof(float);   // 99584
    cudaFuncSetAttribute(attn_kernel, cudaFuncAttributeMaxDynamicSharedMemorySize, ATTN_SMEM);
    attn_kernel<<<dim3(SQ / 64, BB * HH), 256, ATTN_SMEM>>>(q, k, v, chi, clo);

    // --- output projection straight into d_out ---
    gemm_mma<0><<<gg, 256, GEMM_SMEM>>>(chi, clo,
        wthi + 3 * (size_t)DD * DD, wtlo + 3 * (size_t)DD * DD, bo, nullptr, out);
}